// round 15
// baseline (speedup 1.0000x reference)
#include <cuda_runtime.h>

#define IMG   64
#define OUTW  61
#define NB    256
#define NBLK  128              // single wave: 128 CTAs x 512 thr, 2 images/CTA
#define NOUT  (OUTW * OUTW)
#define NGROUP 8               // 16 CTAs per group word

// Two-level fused count+sum accumulators. Each 64-bit word: bits[52:64) =
// arrival count, bits[0:52) = fixed-point (x 2^20) sigmoid sum. Integer adds
// commute -> bit-deterministic result regardless of CTA completion order.
// All values flow through atomic RETURN values (total modification order per
// address), so no fences/acquire loads are needed anywhere. Group words are
// 128B apart (distinct LTS slices); only 16 CTAs touch each -> 8x less
// same-line pressure than the R11/R12 single-line design. Every word is
// rearmed to 0 by exact subtraction before kernel end -> graph-replayable.
struct __align__(128) AccWord { unsigned long long v; };
__device__ AccWord            g_group[NGROUP];   // zero-initialized
__device__ unsigned long long g_final = 0ULL;

#define TICKET_ONE (1ULL << 52)
#define SUM_MASK   (TICKET_ONE - 1ULL)
#define FIX_SCALE  1048576.0f            // 2^20

__device__ __forceinline__ float fast_sigmoid(float x)
{
    float t;
    asm("tanh.approx.f32 %0, %1;" : "=f"(t) : "f"(0.5f * x));
    return fmaf(0.5f, t, 0.5f);          // sigmoid(x) = 0.5*tanh(x/2) + 0.5
}

__global__ void __launch_bounds__(512) conv_hybrid_fused(
    const float* __restrict__ data,
    const float* __restrict__ conv_w,
    const float* __restrict__ conv_b,
    float* __restrict__ out)
{
    __shared__ float red[16];

    const int t     = threadIdx.x;
    const int lane  = t & 31;
    const int wid   = t >> 5;                 // 0..15
    const int local = t & 255;
    const int b     = (blockIdx.x << 1) | (t >> 8);   // image for this half-block

    // Thread -> 4x4 output patch: rows r0..r0+3, cols 4g..4g+3.
    const int g  = local & 15;
    const int r0 = (local >> 4) << 2;         // 0,4,...,60

    // Weights + bias -> registers (uniform broadcast loads, no barrier).
    const float4 W0 = __ldg((const float4*)conv_w + 0);
    const float4 W1 = __ldg((const float4*)conv_w + 1);
    const float4 W2 = __ldg((const float4*)conv_w + 2);
    const float4 W3 = __ldg((const float4*)conv_w + 3);
    const float bias = __ldg(conv_b);

    // 14 front-batched LDG.128: 7 input rows x 8 cols (two overlapping float4).
    // Rows clamped at 63 (feed only invalid outputs); for g==15 the halo
    // float4 aliases the main one (halo cols feed only discarded acc1..acc3).
    const float* img  = data + ((size_t)b << 12) + (g << 2);
    const int    hoff = (g < 15) ? 4 : 0;
    float4 L[7], H[7];
    #pragma unroll
    for (int k = 0; k < 7; k++) {
        int row = r0 + k; if (row > 63) row = 63;
        const float* p = img + row * IMG;
        L[k] = *(const float4*)p;
        H[k] = *(const float4*)(p + hoff);
    }

    float lsum = 0.0f;
    #pragma unroll
    for (int rr = 0; rr < 4; rr++) {
        float a0 = bias, a1 = bias, a2 = bias, a3 = bias;
        #pragma unroll
        for (int dr = 0; dr < 4; dr++) {
            const float4 F = L[rr + dr];
            const float4 X = H[rr + dr];
            const float4 W = (dr == 0) ? W0 : (dr == 1) ? W1 : (dr == 2) ? W2 : W3;
            a0 = fmaf(F.x, W.x, fmaf(F.y, W.y, fmaf(F.z, W.z, fmaf(F.w, W.w, a0))));
            a1 = fmaf(F.y, W.x, fmaf(F.z, W.y, fmaf(F.w, W.z, fmaf(X.x, W.w, a1))));
            a2 = fmaf(F.z, W.x, fmaf(F.w, W.y, fmaf(X.x, W.z, fmaf(X.y, W.w, a2))));
            a3 = fmaf(F.w, W.x, fmaf(X.x, W.y, fmaf(X.y, W.z, fmaf(X.z, W.w, a3))));
        }
        if (r0 + rr < OUTW) {                       // output row valid
            lsum += fast_sigmoid(a0);               // col 4g always < 61
            if (g < 15)                             // cols 4g+1..4g+3
                lsum += fast_sigmoid(a1) + fast_sigmoid(a2) + fast_sigmoid(a3);
        }
    }

    // Deterministic intra-warp tree reduce, then one smem slot per warp.
    #pragma unroll
    for (int o = 16; o; o >>= 1)
        lsum += __shfl_xor_sync(0xffffffffu, lsum, o);
    if (lane == 0) red[wid] = lsum;
    __syncthreads();                                // the ONLY block barrier

    if (wid != 0) return;

    // ── Warp 0: CTA partial -> fixed point -> level-1 group atomic ──
    float v = (lane < 16) ? red[lane] : 0.0f;
    #pragma unroll
    for (int o = 16; o; o >>= 1)
        v += __shfl_xor_sync(0xffffffffu, v, o);

    unsigned long long grand = 0ULL;
    int role = 0;                                   // 0=loser 1=winner
    if (lane == 0) {
        const unsigned long long fixed =
            (unsigned long long)llrintf(v * FIX_SCALE);
        unsigned long long* gword = &g_group[blockIdx.x & (NGROUP - 1)].v;
        const unsigned long long r1 = atomicAdd(gword, TICKET_ONE + fixed);

        if ((unsigned int)(r1 >> 52) == 15u) {      // 16th arrival: semifinalist
            const unsigned long long gtotal = (r1 & SUM_MASK) + fixed;
            // Rearm own group word by exact subtraction (16 tickets + sum).
            atomicAdd(gword,
                (unsigned long long)(0ULL - (TICKET_ONE * 16ULL + gtotal)));
            // Level-2 final atomic.
            const unsigned long long r2 =
                atomicAdd(&g_final, TICKET_ONE + gtotal);
            if ((unsigned int)(r2 >> 52) == (NGROUP - 1u)) {   // 8th: winner
                grand = (r2 & SUM_MASK) + gtotal;
                role  = 1;
            }
        }
    }
    role = __shfl_sync(0xffffffffu, role, 0);
    if (!role) return;

    // ── Winner warp: grand total already in-register — zero loads ──
    grand = __shfl_sync(0xffffffffu, grand, 0);

    // Quantum term: the state stays exactly uniform under RX(theta in
    // {0, float32(pi)}) and the CX chain, so qexp = (c^2+s^2)^k - 1 and
    // c^2+s^2 == 1.0f exactly in fp32 -> qexp == 0 for every batch element.
    // Hence out[b] = 0.5 * classical_mean for all b.
    const float sum = (float)grand * (1.0f / FIX_SCALE);
    const float r   = 0.5f * sum * (1.0f / ((float)NB * (float)NOUT));
    const float4 rv = make_float4(r, r, r, r);
    float4* o4 = (float4*)out;                      // 256 floats = 64 float4
    o4[lane]      = rv;
    o4[lane + 32] = rv;

    // Rearm final word by exact subtraction (8 tickets + grand sum).
    if (lane == 0)
        atomicAdd(&g_final,
            (unsigned long long)(0ULL - (TICKET_ONE * NGROUP + grand)));
}

extern "C" void kernel_launch(void* const* d_in, const int* in_sizes, int n_in,
                              void* d_out, int out_size)
{
    const float* data   = (const float*)d_in[0];
    const float* conv_w = (const float*)d_in[1];
    const float* conv_b = (const float*)d_in[2];
    float* out = (float*)d_out;

    conv_hybrid_fused<<<NBLK, 512>>>(data, conv_w, conv_b, out);
}

// round 16
// speedup vs baseline: 1.0814x; 1.0814x over previous
#include <cuda_runtime.h>

#define IMG     64
#define OUTW    61
#define NB      256
#define NBLK    256            // 1 image/CTA, 512 thr, 2 CTAs/SM -> single wave
#define NOUT    (OUTW * OUTW)
#define NGROUP  16             // 16 CTAs per group word

// Two-level fused count+sum accumulators. Each 64-bit word: bits[52:64) =
// arrival count, bits[0:52) = fixed-point (x 2^20) sigmoid sum. Integer adds
// commute -> bit-deterministic regardless of arrival order. All values flow
// through atomic RETURN values (total modification order per address) -> no
// fences needed. Group words 128B apart; 16 CTAs per word. All words rearmed
// to 0 by exact subtraction before kernel end -> graph-replayable.
struct __align__(128) AccWord { unsigned long long v; };
__device__ AccWord            g_group[NGROUP];   // zero-initialized
__device__ unsigned long long g_final = 0ULL;

#define TICKET_ONE (1ULL << 52)
#define SUM_MASK   (TICKET_ONE - 1ULL)
#define FIX_SCALE  1048576.0f            // 2^20

__device__ __forceinline__ float fast_sigmoid(float x)
{
    float t;
    asm("tanh.approx.f32 %0, %1;" : "=f"(t) : "f"(0.5f * x));
    return fmaf(0.5f, t, 0.5f);          // sigmoid(x) = 0.5*tanh(x/2) + 0.5
}

__global__ void __launch_bounds__(512, 2) conv_hybrid_fused(
    const float* __restrict__ data,
    const float* __restrict__ conv_w,
    const float* __restrict__ conv_b,
    float* __restrict__ out)
{
    __shared__ float red[16];

    const int t    = threadIdx.x;
    const int lane = t & 31;
    const int wid  = t >> 5;                  // 0..15
    const int b    = blockIdx.x;              // image

    // Thread -> 2x4 output patch: rows r0,r0+1, cols 4g..4g+3.
    const int g  = t & 15;
    const int r0 = (t >> 4) << 1;             // 0,2,...,62

    // Weights + bias -> registers (uniform broadcast loads, no barrier).
    const float4 W0 = __ldg((const float4*)conv_w + 0);
    const float4 W1 = __ldg((const float4*)conv_w + 1);
    const float4 W2 = __ldg((const float4*)conv_w + 2);
    const float4 W3 = __ldg((const float4*)conv_w + 3);
    const float bias = __ldg(conv_b);

    // 5 front-batched LDG.128: input rows r0..r0+4, cols 4g..4g+3.
    // Row clamp at 63 feeds only invalid outputs. Halo cols come from the
    // lane+1 neighbor via shuffle (validated in R6): g==15 / lane 31 receive
    // garbage, but those values feed only acc1..acc3, discarded at g==15.
    const float* img = data + ((size_t)b << 12) + (g << 2);
    float4 L[5];
    #pragma unroll
    for (int k = 0; k < 5; k++) {
        int row = r0 + k; if (row > 63) row = 63;
        L[k] = *(const float4*)(img + row * IMG);
    }

    float x0 = bias, x1 = bias, x2 = bias, x3 = bias;   // output row r0
    float y0 = bias, y1 = bias, y2 = bias, y3 = bias;   // output row r0+1

    #pragma unroll
    for (int k = 0; k < 5; k++) {
        const float4 F = L[k];
        const float h4 = __shfl_down_sync(0xffffffffu, F.x, 1);
        const float h5 = __shfl_down_sync(0xffffffffu, F.y, 1);
        const float h6 = __shfl_down_sync(0xffffffffu, F.z, 1);
        if (k < 4) {            // contributes to row r0 with weight row k
            const float4 W = (k == 0) ? W0 : (k == 1) ? W1 : (k == 2) ? W2 : W3;
            x0 = fmaf(F.x, W.x, fmaf(F.y, W.y, fmaf(F.z, W.z, fmaf(F.w, W.w, x0))));
            x1 = fmaf(F.y, W.x, fmaf(F.z, W.y, fmaf(F.w, W.z, fmaf(h4,  W.w, x1))));
            x2 = fmaf(F.z, W.x, fmaf(F.w, W.y, fmaf(h4,  W.z, fmaf(h5,  W.w, x2))));
            x3 = fmaf(F.w, W.x, fmaf(h4,  W.y, fmaf(h5,  W.z, fmaf(h6,  W.w, x3))));
        }
        if (k >= 1) {           // contributes to row r0+1 with weight row k-1
            const float4 W = (k == 1) ? W0 : (k == 2) ? W1 : (k == 3) ? W2 : W3;
            y0 = fmaf(F.x, W.x, fmaf(F.y, W.y, fmaf(F.z, W.z, fmaf(F.w, W.w, y0))));
            y1 = fmaf(F.y, W.x, fmaf(F.z, W.y, fmaf(F.w, W.z, fmaf(h4,  W.w, y1))));
            y2 = fmaf(F.z, W.x, fmaf(F.w, W.y, fmaf(h4,  W.z, fmaf(h5,  W.w, y2))));
            y3 = fmaf(F.w, W.x, fmaf(h4,  W.y, fmaf(h5,  W.z, fmaf(h6,  W.w, y3))));
        }
    }

    // Valid outputs: col 4g always < 61; cols 4g+1..3 iff g<15.
    // Row r0 valid iff r0 < 61 (fails only at r0=62); row r0+1 iff r0+1 < 61.
    float lsum = 0.0f;
    if (r0 < OUTW) {
        lsum = fast_sigmoid(x0);
        if (g < 15) lsum += fast_sigmoid(x1) + fast_sigmoid(x2) + fast_sigmoid(x3);
    }
    if (r0 + 1 < OUTW) {
        lsum += fast_sigmoid(y0);
        if (g < 15) lsum += fast_sigmoid(y1) + fast_sigmoid(y2) + fast_sigmoid(y3);
    }

    // Deterministic intra-warp tree reduce, then one smem slot per warp.
    #pragma unroll
    for (int o = 16; o; o >>= 1)
        lsum += __shfl_xor_sync(0xffffffffu, lsum, o);
    if (lane == 0) red[wid] = lsum;
    __syncthreads();                                // the ONLY block barrier

    if (wid != 0) return;

    // ── Warp 0: CTA partial -> fixed point -> level-1 group atomic ──
    float v = (lane < 16) ? red[lane] : 0.0f;
    #pragma unroll
    for (int o = 16; o; o >>= 1)
        v += __shfl_xor_sync(0xffffffffu, v, o);

    unsigned long long grand = 0ULL;
    int role = 0;
    if (lane == 0) {
        const unsigned long long fixed =
            (unsigned long long)llrintf(v * FIX_SCALE);
        unsigned long long* gword = &g_group[b & (NGROUP - 1)].v;
        const unsigned long long r1 = atomicAdd(gword, TICKET_ONE + fixed);

        if ((unsigned int)(r1 >> 52) == 15u) {      // 16th arrival: semifinalist
            const unsigned long long gtotal = (r1 & SUM_MASK) + fixed;
            // Rearm own group word by exact subtraction (16 tickets + sum).
            atomicAdd(gword,
                (unsigned long long)(0ULL - (TICKET_ONE * 16ULL + gtotal)));
            // Level-2 final atomic.
            const unsigned long long r2 =
                atomicAdd(&g_final, TICKET_ONE + gtotal);
            if ((unsigned int)(r2 >> 52) == (NGROUP - 1u)) {   // 16th: winner
                grand = (r2 & SUM_MASK) + gtotal;
                role  = 1;
            }
        }
    }
    role = __shfl_sync(0xffffffffu, role, 0);
    if (!role) return;

    // ── Winner warp: grand total already in-register — zero loads ──
    grand = __shfl_sync(0xffffffffu, grand, 0);

    // Quantum term: the state stays exactly uniform under RX(theta in
    // {0, float32(pi)}) and the CX chain, so qexp = (c^2+s^2)^k - 1 and
    // c^2+s^2 == 1.0f exactly in fp32 -> qexp == 0 for every batch element.
    // Hence out[b] = 0.5 * classical_mean for all b.
    const float sum = (float)grand * (1.0f / FIX_SCALE);
    const float r   = 0.5f * sum * (1.0f / ((float)NB * (float)NOUT));
    const float4 rv = make_float4(r, r, r, r);
    float4* o4 = (float4*)out;                      // 256 floats = 64 float4
    o4[lane]      = rv;
    o4[lane + 32] = rv;

    // Rearm final word by exact subtraction (16 tickets + grand sum).
    if (lane == 0)
        atomicAdd(&g_final,
            (unsigned long long)(0ULL - (TICKET_ONE * NGROUP + grand)));
}

extern "C" void kernel_launch(void* const* d_in, const int* in_sizes, int n_in,
                              void* d_out, int out_size)
{
    const float* data   = (const float*)d_in[0];
    const float* conv_w = (const float*)d_in[1];
    const float* conv_b = (const float*)d_in[2];
    float* out = (float*)d_out;

    conv_hybrid_fused<<<NBLK, 512>>>(data, conv_w, conv_b, out);
}

// round 17
// speedup vs baseline: 1.3413x; 1.2404x over previous
#include <cuda_runtime.h>

#define IMG     64
#define OUTW    61
#define NB      256
#define NBLK    1024           // quarter-image per CTA, 128 thr, ~7 CTAs/SM max
#define NOUT    (OUTW * OUTW)
#define NGROUP  32             // 32 CTAs per group word

// Two-level fused count+sum accumulators. Each 64-bit word: bits[52:64) =
// arrival count, bits[0:52) = fixed-point (x 2^20) sigmoid sum. Integer adds
// commute -> bit-deterministic regardless of arrival order. All values flow
// through atomic RETURN values (total modification order per address) -> no
// fences needed. Group words 128B apart; 32 CTAs per word. All words rearmed
// to 0 by exact subtraction before kernel end -> graph-replayable.
struct __align__(128) AccWord { unsigned long long v; };
__device__ AccWord            g_group[NGROUP];   // zero-initialized
__device__ unsigned long long g_final = 0ULL;

#define TICKET_ONE (1ULL << 52)
#define SUM_MASK   (TICKET_ONE - 1ULL)
#define FIX_SCALE  1048576.0f            // 2^20

__device__ __forceinline__ float fast_sigmoid(float x)
{
    float t;
    asm("tanh.approx.f32 %0, %1;" : "=f"(t) : "f"(0.5f * x));
    return fmaf(0.5f, t, 0.5f);          // sigmoid(x) = 0.5*tanh(x/2) + 0.5
}

__global__ void __launch_bounds__(128, 8) conv_hybrid_fused(
    const float* __restrict__ data,
    const float* __restrict__ conv_w,
    const float* __restrict__ conv_b,
    float* __restrict__ out)
{
    __shared__ float red[4];

    const int t    = threadIdx.x;
    const int lane = t & 31;
    const int wid  = t >> 5;                  // 0..3
    const int bid  = blockIdx.x;
    const int b    = bid >> 2;                // image
    const int s    = bid & 3;                 // quarter: output rows 16s..16s+15

    // Thread -> 2x4 output patch: rows R, R+1 where R = 16s + 2*(t>>4),
    // cols 4g..4g+3.
    const int g  = t & 15;
    const int r0 = (t >> 4) << 1;             // 0,2,...,14 within quarter
    const int R  = (s << 4) + r0;             // absolute output row

    // Weights + bias -> registers (uniform broadcast loads, no barrier).
    const float4 W0 = __ldg((const float4*)conv_w + 0);
    const float4 W1 = __ldg((const float4*)conv_w + 1);
    const float4 W2 = __ldg((const float4*)conv_w + 2);
    const float4 W3 = __ldg((const float4*)conv_w + 3);
    const float bias = __ldg(conv_b);

    // 5 front-batched LDG.128: input rows R..R+4, cols 4g..4g+3. Row clamp at
    // 63 feeds only invalid outputs. Halo cols come from the lane+1 neighbor
    // via shuffle (validated R6/R15): g==15 / lane 31 receive garbage, but
    // those values feed only acc1..acc3, discarded at g==15.
    const float* img = data + ((size_t)b << 12) + (g << 2);
    float4 L[5];
    #pragma unroll
    for (int k = 0; k < 5; k++) {
        int row = R + k; if (row > 63) row = 63;
        L[k] = *(const float4*)(img + row * IMG);
    }

    float x0 = bias, x1 = bias, x2 = bias, x3 = bias;   // output row R
    float y0 = bias, y1 = bias, y2 = bias, y3 = bias;   // output row R+1

    #pragma unroll
    for (int k = 0; k < 5; k++) {
        const float4 F = L[k];
        const float h4 = __shfl_down_sync(0xffffffffu, F.x, 1);
        const float h5 = __shfl_down_sync(0xffffffffu, F.y, 1);
        const float h6 = __shfl_down_sync(0xffffffffu, F.z, 1);
        if (k < 4) {            // contributes to row R with weight row k
            const float4 W = (k == 0) ? W0 : (k == 1) ? W1 : (k == 2) ? W2 : W3;
            x0 = fmaf(F.x, W.x, fmaf(F.y, W.y, fmaf(F.z, W.z, fmaf(F.w, W.w, x0))));
            x1 = fmaf(F.y, W.x, fmaf(F.z, W.y, fmaf(F.w, W.z, fmaf(h4,  W.w, x1))));
            x2 = fmaf(F.z, W.x, fmaf(F.w, W.y, fmaf(h4,  W.z, fmaf(h5,  W.w, x2))));
            x3 = fmaf(F.w, W.x, fmaf(h4,  W.y, fmaf(h5,  W.z, fmaf(h6,  W.w, x3))));
        }
        if (k >= 1) {           // contributes to row R+1 with weight row k-1
            const float4 W = (k == 1) ? W0 : (k == 2) ? W1 : (k == 3) ? W2 : W3;
            y0 = fmaf(F.x, W.x, fmaf(F.y, W.y, fmaf(F.z, W.z, fmaf(F.w, W.w, y0))));
            y1 = fmaf(F.y, W.x, fmaf(F.z, W.y, fmaf(F.w, W.z, fmaf(h4,  W.w, y1))));
            y2 = fmaf(F.z, W.x, fmaf(F.w, W.y, fmaf(h4,  W.z, fmaf(h5,  W.w, y2))));
            y3 = fmaf(F.w, W.x, fmaf(h4,  W.y, fmaf(h5,  W.z, fmaf(h6,  W.w, y3))));
        }
    }

    // Valid outputs: col 4g always < 61; cols 4g+1..3 iff g<15.
    float lsum = 0.0f;
    if (R < OUTW) {
        lsum = fast_sigmoid(x0);
        if (g < 15) lsum += fast_sigmoid(x1) + fast_sigmoid(x2) + fast_sigmoid(x3);
    }
    if (R + 1 < OUTW) {
        lsum += fast_sigmoid(y0);
        if (g < 15) lsum += fast_sigmoid(y1) + fast_sigmoid(y2) + fast_sigmoid(y3);
    }

    // Deterministic intra-warp tree reduce, then one smem slot per warp.
    #pragma unroll
    for (int o = 16; o; o >>= 1)
        lsum += __shfl_xor_sync(0xffffffffu, lsum, o);
    if (lane == 0) red[wid] = lsum;
    __syncthreads();                                // the ONLY block barrier

    if (wid != 0) return;

    // ── Warp 0: CTA partial -> fixed point -> level-1 group atomic ──
    float v = (lane < 4) ? red[lane] : 0.0f;
    v += __shfl_xor_sync(0xffffffffu, v, 2);
    v += __shfl_xor_sync(0xffffffffu, v, 1);        // lane0 holds CTA total

    unsigned long long grand = 0ULL;
    int role = 0;
    if (lane == 0) {
        const unsigned long long fixed =
            (unsigned long long)llrintf(v * FIX_SCALE);
        unsigned long long* gword = &g_group[bid & (NGROUP - 1)].v;
        const unsigned long long r1 = atomicAdd(gword, TICKET_ONE + fixed);

        if ((unsigned int)(r1 >> 52) == 31u) {      // 32nd arrival: semifinalist
            const unsigned long long gtotal = (r1 & SUM_MASK) + fixed;
            // Rearm own group word by exact subtraction (32 tickets + sum).
            atomicAdd(gword,
                (unsigned long long)(0ULL - (TICKET_ONE * 32ULL + gtotal)));
            // Level-2 final atomic.
            const unsigned long long r2 =
                atomicAdd(&g_final, TICKET_ONE + gtotal);
            if ((unsigned int)(r2 >> 52) == (NGROUP - 1u)) {   // 32nd: winner
                grand = (r2 & SUM_MASK) + gtotal;
                role  = 1;
            }
        }
    }
    role = __shfl_sync(0xffffffffu, role, 0);
    if (!role) return;

    // ── Winner warp: grand total already in-register — zero loads ──
    grand = __shfl_sync(0xffffffffu, grand, 0);

    // Quantum term: the state stays exactly uniform under RX(theta in
    // {0, float32(pi)}) and the CX chain, so qexp = (c^2+s^2)^k - 1 and
    // c^2+s^2 == 1.0f exactly in fp32 -> qexp == 0 for every batch element.
    // Hence out[b] = 0.5 * classical_mean for all b.
    const float sum = (float)grand * (1.0f / FIX_SCALE);
    const float r   = 0.5f * sum * (1.0f / ((float)NB * (float)NOUT));
    const float4 rv = make_float4(r, r, r, r);
    float4* o4 = (float4*)out;                      // 256 floats = 64 float4
    o4[lane]      = rv;
    o4[lane + 32] = rv;

    // Rearm final word by exact subtraction (32 tickets + grand sum).
    if (lane == 0)
        atomicAdd(&g_final,
            (unsigned long long)(0ULL - (TICKET_ONE * NGROUP + grand)));
}

extern "C" void kernel_launch(void* const* d_in, const int* in_sizes, int n_in,
                              void* d_out, int out_size)
{
    const float* data   = (const float*)d_in[0];
    const float* conv_w = (const float*)d_in[1];
    const float* conv_b = (const float*)d_in[2];
    float* out = (float*)d_out;

    conv_hybrid_fused<<<NBLK, 128>>>(data, conv_w, conv_b, out);
}